// round 13
// baseline (speedup 1.0000x reference)
#include <cuda_runtime.h>
#include <cuda_fp16.h>
#include <cstdint>

// Capsule layer (R12): prep folded into conv.
//   conv:  fp16 mma.sync m16n8k16 GEMM votes[i][128px,128cf]; fp32 acc,
//          fp16 vote store. Each block builds its W fragment tile in smem
//          from raw fp32 W (staging buffer aliases the x-tile buffer).
//   routing: fp32 dynamic routing, one warp per pixel.
//
//   x [32,32,32,8,16] f32   W [8,3,3,16,128] f32   b [1,1,8,16] f32
//   out [32,32,32,8,16] f32

#define EPS_SQ 1e-7f
#define XH_PITCH 232        // half2 units; 232 % 32 == 8 -> conflict-free LDS

__device__ __half g_votes[32768 * 1024];            // [px][i*128+cf] fp16

__device__ __forceinline__ void mma16(float c[4], const uint4& a, const uint2& b) {
    asm volatile(
        "mma.sync.aligned.m16n8k16.row.col.f32.f16.f16.f32 "
        "{%0,%1,%2,%3}, {%4,%5,%6,%7}, {%8,%9}, {%0,%1,%2,%3};"
        : "+f"(c[0]), "+f"(c[1]), "+f"(c[2]), "+f"(c[3])
        : "r"(a.x), "r"(a.y), "r"(a.z), "r"(a.w), "r"(b.x), "r"(b.y));
}
__device__ __forceinline__ uint32_t h2u(__half2 h) {
    return *reinterpret_cast<uint32_t*>(&h);
}

// ---- K1: conv votes GEMM. grid (256 m-blocks, 8 i), 512 threads ----
// Block = 128 px (4 h-rows x 32 w of batch mblk>>3), 128 cf, one capsule i.
// 16 warps: wm = wid&3 (h-row, M32), wn = wid>>2 (N32 = 4 n8 tiles).
// K = 144 = 9 k16 steps; step kk == tap (ky,kx) = (kk/3, kk%3), 16 fins.
//
// s_w fragment layout: word (kk*16+nt)*32 + lane, lane = g*4+c4 with
// g = cf&7 (cf = nt*8+g), c4 = k-pair; .x = half2(W[fin=2c4][cf], W[2c4+1][cf]),
// .y = same fin+8.
__global__ __launch_bounds__(512, 2)
void conv_votes_kernel(const float* __restrict__ x, const float* __restrict__ W)
{
    __shared__ uint32_t s_buf[2048];     // raw W slice staging, then x tile
    __shared__ uint2    s_w[9 * 512];    // W fragments for this i (36 KB)

    const int t = threadIdx.x, lane = t & 31, wid = t >> 5;
    const int mblk = blockIdx.x, i = blockIdx.y;
    const int b = mblk >> 3, h0 = (mblk & 7) << 2;

    const int g = lane >> 2, c4 = lane & 3;

    // ---- build W fragments: per tap, stage 8 KB raw slice, pack frags ----
    {
        const float4* Wi4 = reinterpret_cast<const float4*>(W) + (size_t)i * 4608;
        const int nt = wid;                          // t>>5 = fragment nt
        const int cf = nt * 8 + g;
        #pragma unroll
        for (int kk = 0; kk < 9; kk++) {
            reinterpret_cast<float4*>(s_buf)[t] = Wi4[kk * 512 + t];
            __syncthreads();
            const float* p = reinterpret_cast<const float*>(s_buf) + cf;
            uint2 o;
            o.x = h2u(__floats2half2_rn(p[(2 * c4) * 128], p[(2 * c4 + 1) * 128]));
            o.y = h2u(__floats2half2_rn(p[(2 * c4 + 8) * 128], p[(2 * c4 + 9) * 128]));
            __syncthreads();                          // all reads done before next stage
            s_w[kk * 512 + t] = o;
        }
    }

    // ---- x tile (6 rows x 34 cols x 16 fin) -> packed half2 in s_buf ----
    uint32_t* x_h = s_buf;                            // [finp 8][pix 204], pitch 232
    for (int e4 = t; e4 < 816; e4 += 512) {
        int pix = e4 >> 2, q = e4 & 3;                // q covers fin 4q..4q+3
        int r = pix / 34, c = pix - r * 34;
        int hh = h0 + r - 1, ww = c - 1;
        float4 v = make_float4(0.f, 0.f, 0.f, 0.f);
        if (hh >= 0 && hh < 32 && ww >= 0 && ww < 32)
            v = reinterpret_cast<const float4*>(x)
                  [((b * 32 + hh) * 32 + ww) * 32 + i * 4 + q];
        x_h[(q * 2 + 0) * XH_PITCH + pix] = h2u(__floats2half2_rn(v.x, v.y));
        x_h[(q * 2 + 1) * XH_PITCH + pix] = h2u(__floats2half2_rn(v.z, v.w));
    }
    __syncthreads();

    const int wm = wid & 3, wn = wid >> 2;

    float acc[2][4][4];
    #pragma unroll
    for (int mt = 0; mt < 2; mt++)
        #pragma unroll
        for (int n = 0; n < 4; n++)
            #pragma unroll
            for (int j = 0; j < 4; j++) acc[mt][n][j] = 0.f;

    #pragma unroll
    for (int kk = 0; kk < 9; kk++) {
        const int ky = kk / 3, kx = kk - ky * 3;
        const int pbase = (wm + ky) * 34 + kx + g;
        uint4 a[2];
        #pragma unroll
        for (int mt = 0; mt < 2; mt++) {
            const int p0 = pbase + mt * 16;
            a[mt].x = x_h[c4 * XH_PITCH + p0];
            a[mt].y = x_h[c4 * XH_PITCH + p0 + 8];
            a[mt].z = x_h[(c4 + 4) * XH_PITCH + p0];
            a[mt].w = x_h[(c4 + 4) * XH_PITCH + p0 + 8];
        }
        #pragma unroll
        for (int n = 0; n < 4; n++) {
            uint2 bb = s_w[(kk * 16 + wn * 4 + n) * 32 + lane];
            mma16(acc[0][n], a[0], bb);
            mma16(acc[1][n], a[1], bb);
        }
    }

    // store votes fp16: u32 idx = px*512 + i*64 + (wn*4+n)*4 + c4
    uint32_t* vp = reinterpret_cast<uint32_t*>(g_votes) +
                   (size_t)(mblk * 128) * 512 + i * 64 + wn * 16 + c4;
    #pragma unroll
    for (int mt = 0; mt < 2; mt++) {
        const int m0 = wm * 32 + mt * 16 + g;
        #pragma unroll
        for (int n = 0; n < 4; n++) {
            vp[(size_t)m0 * 512 + n * 4] =
                h2u(__floats2half2_rn(acc[mt][n][0], acc[mt][n][1]));
            vp[(size_t)(m0 + 8) * 512 + n * 4] =
                h2u(__floats2half2_rn(acc[mt][n][2], acc[mt][n][3]));
        }
    }
}

// ---- K2: routing. grid 4096, 256 threads; warp w routes px = blk*8+w ----
__global__ __launch_bounds__(256)
void routing_kernel(const float* __restrict__ bias, float* __restrict__ out)
{
    const int t = threadIdx.x, lane = t & 31, wid = t >> 5;
    const int px = blockIdx.x * 8 + wid;

    const float4 bv = reinterpret_cast<const float4*>(bias)[lane];
    const uint2* vg = reinterpret_cast<const uint2*>(g_votes) + (size_t)px * 256;

    float4 v[8];
    #pragma unroll
    for (int i = 0; i < 8; i++) {
        uint2 raw = vg[i * 32 + lane];
        float2 f01 = __half22float2(*reinterpret_cast<__half2*>(&raw.x));
        float2 f23 = __half22float2(*reinterpret_cast<__half2*>(&raw.y));
        v[i] = make_float4(f01.x, f01.y, f23.x, f23.y);
    }

    float logit[8];
    #pragma unroll
    for (int i = 0; i < 8; i++) logit[i] = 0.f;
    float4 act = make_float4(0.f, 0.f, 0.f, 0.f);

    #pragma unroll
    for (int r = 0; r < 3; r++) {
        float route[8];
        if (r == 0) {
            #pragma unroll
            for (int i = 0; i < 8; i++) route[i] = 0.125f;   // softmax(0)
        } else {
            #pragma unroll
            for (int i = 0; i < 8; i++) {
                float m = logit[i];
                m = fmaxf(m, __shfl_xor_sync(0xffffffffu, m, 4));
                m = fmaxf(m, __shfl_xor_sync(0xffffffffu, m, 8));
                m = fmaxf(m, __shfl_xor_sync(0xffffffffu, m, 16));
                float e = __expf(logit[i] - m);
                float s = e;
                s += __shfl_xor_sync(0xffffffffu, s, 4);
                s += __shfl_xor_sync(0xffffffffu, s, 8);
                s += __shfl_xor_sync(0xffffffffu, s, 16);
                route[i] = e / s;
            }
        }
        float4 pre = bv;
        #pragma unroll
        for (int i = 0; i < 8; i++) {
            pre.x += route[i] * v[i].x;
            pre.y += route[i] * v[i].y;
            pre.z += route[i] * v[i].z;
            pre.w += route[i] * v[i].w;
        }
        float s2 = pre.x * pre.x + pre.y * pre.y + pre.z * pre.z + pre.w * pre.w;
        s2 += __shfl_xor_sync(0xffffffffu, s2, 1);
        s2 += __shfl_xor_sync(0xffffffffu, s2, 2);
        float scale = s2 / (1.f + s2) * rsqrtf(s2 + EPS_SQ);
        act.x = scale * pre.x;
        act.y = scale * pre.y;
        act.z = scale * pre.z;
        act.w = scale * pre.w;
        if (r < 2) {
            #pragma unroll
            for (int i = 0; i < 8; i++) {
                float d = v[i].x * act.x + v[i].y * act.y +
                          v[i].z * act.z + v[i].w * act.w;
                d += __shfl_xor_sync(0xffffffffu, d, 1);
                d += __shfl_xor_sync(0xffffffffu, d, 2);
                logit[i] += d;
            }
        }
    }

    reinterpret_cast<float4*>(out)[(size_t)px * 32 + lane] = act;
}

extern "C" void kernel_launch(void* const* d_in, const int* in_sizes, int n_in,
                              void* d_out, int out_size)
{
    const float* x    = (const float*)d_in[0];
    const float* Wt   = (const float*)d_in[1];
    const float* bias = (const float*)d_in[2];
    float* out = (float*)d_out;
    (void)in_sizes; (void)n_in; (void)out_size;

    dim3 gridA(256, 8);
    conv_votes_kernel<<<gridA, 512>>>(x, Wt);
    routing_kernel<<<4096, 256>>>(bias, out);
}

// round 14
// speedup vs baseline: 1.4414x; 1.4414x over previous
#include <cuda_runtime.h>
#include <cuda_fp16.h>
#include <cstdint>

// Capsule layer, three-kernel split (R13 = R11 conv/prep + leaner routing):
//   prep:  permute W into fp16 m16n8k16 fragment layout (coalesced via smem)
//   conv:  fp16 mma.sync m16n8k16 GEMM votes[i][128px,128cf]; fp32 acc,
//          fp16 vote store; 512 thr, warp tile M32xN32, 2 blocks/SM.
//   routing: fp32 dynamic routing, one warp per pixel.
//          R13: softmax without max-subtraction (logits bounded ~20) ->
//          48 fewer shfls/px; __fdividef on the route normalization.
//
//   x [32,32,32,8,16] f32   W [8,3,3,16,128] f32   b [1,1,8,16] f32
//   out [32,32,32,8,16] f32

#define EPS_SQ 1e-7f
#define XH_PITCH 232        // half2 units; 232 % 32 == 8 -> conflict-free LDS

__device__ __half   g_votes[32768 * 1024];          // [px][i*128+cf] fp16
__device__ uint2    g_Wfrag[8 * 9 * 16 * 32];       // fp16 B fragments

__device__ __forceinline__ void mma16(float c[4], const uint4& a, const uint2& b) {
    asm volatile(
        "mma.sync.aligned.m16n8k16.row.col.f32.f16.f16.f32 "
        "{%0,%1,%2,%3}, {%4,%5,%6,%7}, {%8,%9}, {%0,%1,%2,%3};"
        : "+f"(c[0]), "+f"(c[1]), "+f"(c[2]), "+f"(c[3])
        : "r"(a.x), "r"(a.y), "r"(a.z), "r"(a.w), "r"(b.x), "r"(b.y));
}
__device__ __forceinline__ uint32_t h2u(__half2 h) {
    return *reinterpret_cast<uint32_t*>(&h);
}

// B fragments: [r = i*9+kk][nt(16)][lane(32)] uint2.
// lane: g = lane>>2 (cf within n8), c4 = lane&3 (k pair); cf = nt*8+g.
// b.x = half2(W[fin=2c4][cf], W[2c4+1][cf]), b.y = same fin+8.
__global__ void prep_weights(const float* __restrict__ W) {
    __shared__ float sW[2048];                    // [fin 16][cf 128]
    const int r = blockIdx.x, t = threadIdx.x;
    const float4* Wg = reinterpret_cast<const float4*>(W) + r * 512;
    reinterpret_cast<float4*>(sW)[t]       = Wg[t];
    reinterpret_cast<float4*>(sW)[t + 256] = Wg[t + 256];
    __syncthreads();
    #pragma unroll
    for (int j = 0; j < 2; j++) {
        int fr = t + j * 256;                     // 0..511
        int lane = fr & 31, nt = fr >> 5;
        int g = lane >> 2, c4 = lane & 3;
        int cf = nt * 8 + g;
        const float* p = sW + cf;
        uint2 o;
        o.x = h2u(__floats2half2_rn(p[(2 * c4) * 128],     p[(2 * c4 + 1) * 128]));
        o.y = h2u(__floats2half2_rn(p[(2 * c4 + 8) * 128], p[(2 * c4 + 9) * 128]));
        g_Wfrag[r * 512 + fr] = o;
    }
}

// ---- K1: conv votes GEMM. grid (256 m-blocks, 8 i), 512 threads ----
// Block = 128 px (4 h-rows x 32 w of batch mblk>>3), 128 cf, one capsule i.
// 16 warps: wm = wid&3 (h-row, M32), wn = wid>>2 (N32 = 4 n8 tiles).
__global__ __launch_bounds__(512, 2)
void conv_votes_kernel(const float* __restrict__ x)
{
    __shared__ uint32_t x_h[8 * XH_PITCH];   // half2 bits: [finp 8][pix 204]
    __shared__ uint2    s_w[9 * 16 * 32];    // W frags for this i (36 KB)

    const int t = threadIdx.x, lane = t & 31, wid = t >> 5;
    const int mblk = blockIdx.x, i = blockIdx.y;
    const int b = mblk >> 3, h0 = (mblk & 7) << 2;

    // stage W fragments: 2304 uint4
    {
        const uint4* gw4 = reinterpret_cast<const uint4*>(g_Wfrag) + i * 2304;
        uint4* sw4 = reinterpret_cast<uint4*>(s_w);
        #pragma unroll
        for (int j = t; j < 2304; j += 512)
            sw4[j] = gw4[j];
    }

    // x tile (6 rows x 34 cols x 16 fin) -> packed half2, zero-pad SAME
    for (int e4 = t; e4 < 816; e4 += 512) {
        int pix = e4 >> 2, q = e4 & 3;       // q covers fin 4q..4q+3
        int r = pix / 34, c = pix - r * 34;
        int hh = h0 + r - 1, ww = c - 1;
        float4 v = make_float4(0.f, 0.f, 0.f, 0.f);
        if (hh >= 0 && hh < 32 && ww >= 0 && ww < 32)
            v = reinterpret_cast<const float4*>(x)
                  [((b * 32 + hh) * 32 + ww) * 32 + i * 4 + q];
        x_h[(q * 2 + 0) * XH_PITCH + pix] = h2u(__floats2half2_rn(v.x, v.y));
        x_h[(q * 2 + 1) * XH_PITCH + pix] = h2u(__floats2half2_rn(v.z, v.w));
    }
    __syncthreads();

    const int g = lane >> 2, c4 = lane & 3;
    const int wm = wid & 3, wn = wid >> 2;

    float acc[2][4][4];
    #pragma unroll
    for (int mt = 0; mt < 2; mt++)
        #pragma unroll
        for (int n = 0; n < 4; n++)
            #pragma unroll
            for (int j = 0; j < 4; j++) acc[mt][n][j] = 0.f;

    #pragma unroll
    for (int kk = 0; kk < 9; kk++) {
        const int ky = kk / 3, kx = kk - ky * 3;
        const int pbase = (wm + ky) * 34 + kx + g;
        uint4 a[2];
        #pragma unroll
        for (int mt = 0; mt < 2; mt++) {
            const int p0 = pbase + mt * 16;
            a[mt].x = x_h[c4 * XH_PITCH + p0];
            a[mt].y = x_h[c4 * XH_PITCH + p0 + 8];
            a[mt].z = x_h[(c4 + 4) * XH_PITCH + p0];
            a[mt].w = x_h[(c4 + 4) * XH_PITCH + p0 + 8];
        }
        #pragma unroll
        for (int n = 0; n < 4; n++) {
            uint2 bb = s_w[(kk * 16 + wn * 4 + n) * 32 + lane];
            mma16(acc[0][n], a[0], bb);
            mma16(acc[1][n], a[1], bb);
        }
    }

    // store votes fp16: u32 idx = px*512 + i*64 + (wn*4+n)*4 + c4
    uint32_t* vp = reinterpret_cast<uint32_t*>(g_votes) +
                   (size_t)(mblk * 128) * 512 + i * 64 + wn * 16 + c4;
    #pragma unroll
    for (int mt = 0; mt < 2; mt++) {
        const int m0 = wm * 32 + mt * 16 + g;
        #pragma unroll
        for (int n = 0; n < 4; n++) {
            vp[(size_t)m0 * 512 + n * 4] =
                h2u(__floats2half2_rn(acc[mt][n][0], acc[mt][n][1]));
            vp[(size_t)(m0 + 8) * 512 + n * 4] =
                h2u(__floats2half2_rn(acc[mt][n][2], acc[mt][n][3]));
        }
    }
}

// ---- K2: routing. grid 4096, 256 threads; warp w routes px = blk*8+w ----
__global__ __launch_bounds__(256)
void routing_kernel(const float* __restrict__ bias, float* __restrict__ out)
{
    const int t = threadIdx.x, lane = t & 31, wid = t >> 5;
    const int px = blockIdx.x * 8 + wid;

    const float4 bv = reinterpret_cast<const float4*>(bias)[lane];
    const uint2* vg = reinterpret_cast<const uint2*>(g_votes) + (size_t)px * 256;

    float4 v[8];
    #pragma unroll
    for (int i = 0; i < 8; i++) {
        uint2 raw = vg[i * 32 + lane];
        float2 f01 = __half22float2(*reinterpret_cast<__half2*>(&raw.x));
        float2 f23 = __half22float2(*reinterpret_cast<__half2*>(&raw.y));
        v[i] = make_float4(f01.x, f01.y, f23.x, f23.y);
    }

    float logit[8];
    #pragma unroll
    for (int i = 0; i < 8; i++) logit[i] = 0.f;
    float4 act = make_float4(0.f, 0.f, 0.f, 0.f);

    #pragma unroll
    for (int r = 0; r < 3; r++) {
        float route[8];
        if (r == 0) {
            #pragma unroll
            for (int i = 0; i < 8; i++) route[i] = 0.125f;   // softmax(0)
        } else {
            // softmax over output capsules c WITHOUT max-subtraction:
            // |logit| <= ~20 (act squash-normed, votes O(1)) -> exp safe in fp32
            #pragma unroll
            for (int i = 0; i < 8; i++) {
                float e = __expf(logit[i]);
                float s = e;
                s += __shfl_xor_sync(0xffffffffu, s, 4);
                s += __shfl_xor_sync(0xffffffffu, s, 8);
                s += __shfl_xor_sync(0xffffffffu, s, 16);
                route[i] = __fdividef(e, s);
            }
        }
        float4 pre = bv;
        #pragma unroll
        for (int i = 0; i < 8; i++) {
            pre.x += route[i] * v[i].x;
            pre.y += route[i] * v[i].y;
            pre.z += route[i] * v[i].z;
            pre.w += route[i] * v[i].w;
        }
        float s2 = pre.x * pre.x + pre.y * pre.y + pre.z * pre.z + pre.w * pre.w;
        s2 += __shfl_xor_sync(0xffffffffu, s2, 1);
        s2 += __shfl_xor_sync(0xffffffffu, s2, 2);
        float scale = s2 / (1.f + s2) * rsqrtf(s2 + EPS_SQ);
        act.x = scale * pre.x;
        act.y = scale * pre.y;
        act.z = scale * pre.z;
        act.w = scale * pre.w;
        if (r < 2) {
            #pragma unroll
            for (int i = 0; i < 8; i++) {
                float d = v[i].x * act.x + v[i].y * act.y +
                          v[i].z * act.z + v[i].w * act.w;
                d += __shfl_xor_sync(0xffffffffu, d, 1);
                d += __shfl_xor_sync(0xffffffffu, d, 2);
                logit[i] += d;
            }
        }
    }

    reinterpret_cast<float4*>(out)[(size_t)px * 32 + lane] = act;
}

extern "C" void kernel_launch(void* const* d_in, const int* in_sizes, int n_in,
                              void* d_out, int out_size)
{
    const float* x    = (const float*)d_in[0];
    const float* Wt   = (const float*)d_in[1];
    const float* bias = (const float*)d_in[2];
    float* out = (float*)d_out;
    (void)in_sizes; (void)n_in; (void)out_size;

    prep_weights<<<72, 256>>>(Wt);
    dim3 gridA(256, 8);
    conv_votes_kernel<<<gridA, 512>>>(x);
    routing_kernel<<<4096, 256>>>(bias, out);
}

// round 15
// speedup vs baseline: 1.5283x; 1.0603x over previous
#include <cuda_runtime.h>
#include <cuda_fp16.h>
#include <cstdint>

// Capsule layer, three-kernel split (R14 = R13 conv/prep + distributed routing):
//   prep:  permute W into fp16 m16n8k16 fragment layout (coalesced via smem)
//   conv:  fp16 mma.sync m16n8k16 GEMM votes[i][128px,128cf]; fp32 acc,
//          fp16 vote store; 512 thr, warp tile M32xN32, 2 blocks/SM.
//   routing: fp32 dynamic routing, one warp per pixel.
//          R14: logits/softmax distributed over the 4 fq lanes (each lane
//          owns capsules i=2fq, 2fq+1): agreement via 6-shfl reduce-scatter,
//          softmax = 2 exps + 6-shfl c-sum + 6-shfl route all-gather.
//          Shfls/px 86 -> 42, exps 16 -> 4, divs 16 -> 4.
//
//   x [32,32,32,8,16] f32   W [8,3,3,16,128] f32   b [1,1,8,16] f32
//   out [32,32,32,8,16] f32

#define EPS_SQ 1e-7f
#define XH_PITCH 232        // half2 units; 232 % 32 == 8 -> conflict-free LDS

__device__ __half   g_votes[32768 * 1024];          // [px][i*128+cf] fp16
__device__ uint2    g_Wfrag[8 * 9 * 16 * 32];       // fp16 B fragments

__device__ __forceinline__ void mma16(float c[4], const uint4& a, const uint2& b) {
    asm volatile(
        "mma.sync.aligned.m16n8k16.row.col.f32.f16.f16.f32 "
        "{%0,%1,%2,%3}, {%4,%5,%6,%7}, {%8,%9}, {%0,%1,%2,%3};"
        : "+f"(c[0]), "+f"(c[1]), "+f"(c[2]), "+f"(c[3])
        : "r"(a.x), "r"(a.y), "r"(a.z), "r"(a.w), "r"(b.x), "r"(b.y));
}
__device__ __forceinline__ uint32_t h2u(__half2 h) {
    return *reinterpret_cast<uint32_t*>(&h);
}

// B fragments: [r = i*9+kk][nt(16)][lane(32)] uint2.
__global__ void prep_weights(const float* __restrict__ W) {
    __shared__ float sW[2048];                    // [fin 16][cf 128]
    const int r = blockIdx.x, t = threadIdx.x;
    const float4* Wg = reinterpret_cast<const float4*>(W) + r * 512;
    reinterpret_cast<float4*>(sW)[t]       = Wg[t];
    reinterpret_cast<float4*>(sW)[t + 256] = Wg[t + 256];
    __syncthreads();
    #pragma unroll
    for (int j = 0; j < 2; j++) {
        int fr = t + j * 256;                     // 0..511
        int lane = fr & 31, nt = fr >> 5;
        int g = lane >> 2, c4 = lane & 3;
        int cf = nt * 8 + g;
        const float* p = sW + cf;
        uint2 o;
        o.x = h2u(__floats2half2_rn(p[(2 * c4) * 128],     p[(2 * c4 + 1) * 128]));
        o.y = h2u(__floats2half2_rn(p[(2 * c4 + 8) * 128], p[(2 * c4 + 9) * 128]));
        g_Wfrag[r * 512 + fr] = o;
    }
}

// ---- K1: conv votes GEMM. grid (256 m-blocks, 8 i), 512 threads ----
__global__ __launch_bounds__(512, 2)
void conv_votes_kernel(const float* __restrict__ x)
{
    __shared__ uint32_t x_h[8 * XH_PITCH];   // half2 bits: [finp 8][pix 204]
    __shared__ uint2    s_w[9 * 16 * 32];    // W frags for this i (36 KB)

    const int t = threadIdx.x, lane = t & 31, wid = t >> 5;
    const int mblk = blockIdx.x, i = blockIdx.y;
    const int b = mblk >> 3, h0 = (mblk & 7) << 2;

    {
        const uint4* gw4 = reinterpret_cast<const uint4*>(g_Wfrag) + i * 2304;
        uint4* sw4 = reinterpret_cast<uint4*>(s_w);
        #pragma unroll
        for (int j = t; j < 2304; j += 512)
            sw4[j] = gw4[j];
    }

    for (int e4 = t; e4 < 816; e4 += 512) {
        int pix = e4 >> 2, q = e4 & 3;
        int r = pix / 34, c = pix - r * 34;
        int hh = h0 + r - 1, ww = c - 1;
        float4 v = make_float4(0.f, 0.f, 0.f, 0.f);
        if (hh >= 0 && hh < 32 && ww >= 0 && ww < 32)
            v = reinterpret_cast<const float4*>(x)
                  [((b * 32 + hh) * 32 + ww) * 32 + i * 4 + q];
        x_h[(q * 2 + 0) * XH_PITCH + pix] = h2u(__floats2half2_rn(v.x, v.y));
        x_h[(q * 2 + 1) * XH_PITCH + pix] = h2u(__floats2half2_rn(v.z, v.w));
    }
    __syncthreads();

    const int g = lane >> 2, c4 = lane & 3;
    const int wm = wid & 3, wn = wid >> 2;

    float acc[2][4][4];
    #pragma unroll
    for (int mt = 0; mt < 2; mt++)
        #pragma unroll
        for (int n = 0; n < 4; n++)
            #pragma unroll
            for (int j = 0; j < 4; j++) acc[mt][n][j] = 0.f;

    #pragma unroll
    for (int kk = 0; kk < 9; kk++) {
        const int ky = kk / 3, kx = kk - ky * 3;
        const int pbase = (wm + ky) * 34 + kx + g;
        uint4 a[2];
        #pragma unroll
        for (int mt = 0; mt < 2; mt++) {
            const int p0 = pbase + mt * 16;
            a[mt].x = x_h[c4 * XH_PITCH + p0];
            a[mt].y = x_h[c4 * XH_PITCH + p0 + 8];
            a[mt].z = x_h[(c4 + 4) * XH_PITCH + p0];
            a[mt].w = x_h[(c4 + 4) * XH_PITCH + p0 + 8];
        }
        #pragma unroll
        for (int n = 0; n < 4; n++) {
            uint2 bb = s_w[(kk * 16 + wn * 4 + n) * 32 + lane];
            mma16(acc[0][n], a[0], bb);
            mma16(acc[1][n], a[1], bb);
        }
    }

    uint32_t* vp = reinterpret_cast<uint32_t*>(g_votes) +
                   (size_t)(mblk * 128) * 512 + i * 64 + wn * 16 + c4;
    #pragma unroll
    for (int mt = 0; mt < 2; mt++) {
        const int m0 = wm * 32 + mt * 16 + g;
        #pragma unroll
        for (int n = 0; n < 4; n++) {
            vp[(size_t)m0 * 512 + n * 4] =
                h2u(__floats2half2_rn(acc[mt][n][0], acc[mt][n][1]));
            vp[(size_t)(m0 + 8) * 512 + n * 4] =
                h2u(__floats2half2_rn(acc[mt][n][2], acc[mt][n][3]));
        }
    }
}

// ---- K2: routing. grid 4096, 256 threads; warp w routes px = blk*8+w ----
// lane = c*4 + fq. Lane owns logits for capsules i = 2fq, 2fq+1 (A, B).
__global__ __launch_bounds__(256)
void routing_kernel(const float* __restrict__ bias, float* __restrict__ out)
{
    const int t = threadIdx.x, lane = t & 31, wid = t >> 5;
    const int px = blockIdx.x * 8 + wid;
    const bool b0 = (lane & 1) != 0;     // fq bit0
    const bool b1 = (lane & 2) != 0;     // fq bit1

    const float4 bv = reinterpret_cast<const float4*>(bias)[lane];
    const uint2* vg = reinterpret_cast<const uint2*>(g_votes) + (size_t)px * 256;

    float4 v[8];
    #pragma unroll
    for (int i = 0; i < 8; i++) {
        uint2 raw = vg[i * 32 + lane];
        float2 f01 = __half22float2(*reinterpret_cast<__half2*>(&raw.x));
        float2 f23 = __half22float2(*reinterpret_cast<__half2*>(&raw.y));
        v[i] = make_float4(f01.x, f01.y, f23.x, f23.y);
    }

    float logitA = 0.f, logitB = 0.f;    // i = 2fq, 2fq+1
    float4 act = make_float4(0.f, 0.f, 0.f, 0.f);
    float route[8];

    #pragma unroll
    for (int r = 0; r < 3; r++) {
        if (r == 0) {
            #pragma unroll
            for (int i = 0; i < 8; i++) route[i] = 0.125f;   // softmax(0)
        } else {
            // distributed softmax (no max-sub; |logit| <~ 20, fp32-safe)
            float eA = __expf(logitA), eB = __expf(logitB);
            float sA = eA, sB = eB;
            sA += __shfl_xor_sync(0xffffffffu, sA, 4);
            sA += __shfl_xor_sync(0xffffffffu, sA, 8);
            sA += __shfl_xor_sync(0xffffffffu, sA, 16);
            sB += __shfl_xor_sync(0xffffffffu, sB, 4);
            sB += __shfl_xor_sync(0xffffffffu, sB, 8);
            sB += __shfl_xor_sync(0xffffffffu, sB, 16);
            float rA = __fdividef(eA, sA);   // route[2fq]
            float rB = __fdividef(eB, sB);   // route[2fq+1]
            // all-gather route[0..7]: xor1 then xor2 over fq bits
            float pA = __shfl_xor_sync(0xffffffffu, rA, 1);
            float pB = __shfl_xor_sync(0xffffffffu, rB, 1);
            // x = route[4g .. 4g+3], g = fq>>1
            float x0 = b0 ? pA : rA, x1 = b0 ? pB : rB;
            float x2 = b0 ? rA : pA, x3 = b0 ? rB : pB;
            float y0 = __shfl_xor_sync(0xffffffffu, x0, 2);
            float y1 = __shfl_xor_sync(0xffffffffu, x1, 2);
            float y2 = __shfl_xor_sync(0xffffffffu, x2, 2);
            float y3 = __shfl_xor_sync(0xffffffffu, x3, 2);
            route[0] = b1 ? y0 : x0;  route[1] = b1 ? y1 : x1;
            route[2] = b1 ? y2 : x2;  route[3] = b1 ? y3 : x3;
            route[4] = b1 ? x0 : y0;  route[5] = b1 ? x1 : y1;
            route[6] = b1 ? x2 : y2;  route[7] = b1 ? x3 : y3;
        }
        float4 pre = bv;
        #pragma unroll
        for (int i = 0; i < 8; i++) {
            pre.x += route[i] * v[i].x;
            pre.y += route[i] * v[i].y;
            pre.z += route[i] * v[i].z;
            pre.w += route[i] * v[i].w;
        }
        float s2 = pre.x * pre.x + pre.y * pre.y + pre.z * pre.z + pre.w * pre.w;
        s2 += __shfl_xor_sync(0xffffffffu, s2, 1);
        s2 += __shfl_xor_sync(0xffffffffu, s2, 2);
        float scale = s2 / (1.f + s2) * rsqrtf(s2 + EPS_SQ);
        act.x = scale * pre.x;
        act.y = scale * pre.y;
        act.z = scale * pre.z;
        act.w = scale * pre.w;
        if (r < 2) {
            // agreement partials (own 4 f's), then reduce-scatter over fq
            float p[8];
            #pragma unroll
            for (int i = 0; i < 8; i++)
                p[i] = v[i].x * act.x + v[i].y * act.y +
                       v[i].z * act.z + v[i].w * act.w;
            // step 1 (xor 1): keep i with bit1(i)==b0; pairs (0,2)(1,3)(4,6)(5,7)
            float s0 = b0 ? p[0] : p[2];
            float s1 = b0 ? p[1] : p[3];
            float s2a = b0 ? p[4] : p[6];
            float s3 = b0 ? p[5] : p[7];
            float q0 = __shfl_xor_sync(0xffffffffu, s0, 1);
            float q1 = __shfl_xor_sync(0xffffffffu, s1, 1);
            float q2 = __shfl_xor_sync(0xffffffffu, s2a, 1);
            float q3 = __shfl_xor_sync(0xffffffffu, s3, 1);
            float u0 = (b0 ? p[2] : p[0]) + q0;   // i = 2*b0
            float u1 = (b0 ? p[3] : p[1]) + q1;   // i = 2*b0+1
            float u2 = (b0 ? p[6] : p[4]) + q2;   // i = 4+2*b0
            float u3 = (b0 ? p[7] : p[5]) + q3;   // i = 4+2*b0+1
            // step 2 (xor 2): keep i with bit2(i)==b1
            float sa = b1 ? u0 : u2;
            float sb = b1 ? u1 : u3;
            float qa = __shfl_xor_sync(0xffffffffu, sa, 2);
            float qb = __shfl_xor_sync(0xffffffffu, sb, 2);
            logitA += (b1 ? u2 : u0) + qa;        // i = 2fq
            logitB += (b1 ? u3 : u1) + qb;        // i = 2fq+1
        }
    }

    reinterpret_cast<float4*>(out)[(size_t)px * 32 + lane] = act;
}

extern "C" void kernel_launch(void* const* d_in, const int* in_sizes, int n_in,
                              void* d_out, int out_size)
{
    const float* x    = (const float*)d_in[0];
    const float* Wt   = (const float*)d_in[1];
    const float* bias = (const float*)d_in[2];
    float* out = (float*)d_out;
    (void)in_sizes; (void)n_in; (void)out_size;

    prep_weights<<<72, 256>>>(Wt);
    dim3 gridA(256, 8);
    conv_votes_kernel<<<gridA, 512>>>(x);
    routing_kernel<<<4096, 256>>>(bias, out);
}